// round 15
// baseline (speedup 1.0000x reference)
#include <cuda_runtime.h>
#include <cuda_fp16.h>
#include <math_constants.h>
#include <cstdint>

#define N_TOK 4096
#define DIM   1024

typedef __half fp16;

// ---------------------------------------------------------------------------
// Scratch (device globals; no allocation allowed)
// ---------------------------------------------------------------------------
__device__ fp16  g_xh [(size_t)N_TOK * DIM];
__device__ fp16  g_xl [(size_t)N_TOK * DIM];
__device__ fp16  g_wqt[(size_t)DIM * DIM];
__device__ fp16  g_wqtl[(size_t)DIM * DIM];
__device__ fp16  g_wkt[(size_t)DIM * DIM];
__device__ fp16  g_wktl[(size_t)DIM * DIM];
__device__ fp16  g_mth[(size_t)DIM * DIM];
__device__ fp16  g_mtl[(size_t)DIM * DIM];
__device__ fp16  g_th [(size_t)N_TOK * DIM];
__device__ fp16  g_tl [(size_t)N_TOK * DIM];
__device__ fp16  g_s16[(size_t)N_TOK * N_TOK];  // approx scores (fp16)
__device__ float g_wp [64 * DIM];                // wvec partials
__device__ float g_w  [DIM];
__device__ float g_v  [N_TOK];

// ---------------------------------------------------------------------------
// Helpers
// ---------------------------------------------------------------------------
__device__ __forceinline__ uint32_t smem_to_u32(const void* p) {
    uint32_t a;
    asm("{ .reg .u64 t; cvta.to.shared.u64 t, %1; cvt.u32.u64 %0, t; }"
        : "=r"(a) : "l"(p));
    return a;
}

__device__ __forceinline__ void cp_async16(uint32_t dst, const void* src) {
    asm volatile("cp.async.cg.shared.global [%0], [%1], 16;"
        :: "r"(dst), "l"(src) : "memory");
}
#define CP_COMMIT() asm volatile("cp.async.commit_group;" ::: "memory")
#define CP_WAIT(n)  asm volatile("cp.async.wait_group %0;" :: "n"(n) : "memory")

__device__ __forceinline__ void ldmx4(uint32_t r[4], uint32_t addr) {
    asm volatile("ldmatrix.sync.aligned.m8n8.x4.shared.b16 {%0,%1,%2,%3}, [%4];"
        : "=r"(r[0]), "=r"(r[1]), "=r"(r[2]), "=r"(r[3]) : "r"(addr));
}

__device__ __forceinline__ void mma_f16(float d[4], const uint32_t a[4],
                                        uint32_t b0, uint32_t b1) {
    asm volatile(
        "mma.sync.aligned.m16n8k16.row.col.f32.f16.f16.f32 "
        "{%0,%1,%2,%3}, {%4,%5,%6,%7}, {%8,%9}, {%0,%1,%2,%3};"
        : "+f"(d[0]), "+f"(d[1]), "+f"(d[2]), "+f"(d[3])
        : "r"(a[0]), "r"(a[1]), "r"(a[2]), "r"(a[3]), "r"(b0), "r"(b1));
}

// fp16-accumulator HMMA (filter-grade)
__device__ __forceinline__ void mma_f16a(uint32_t d[2], const uint32_t a[4],
                                         uint32_t b0, uint32_t b1) {
    asm volatile(
        "mma.sync.aligned.m16n8k16.row.col.f16.f16.f16.f16 "
        "{%0,%1}, {%2,%3,%4,%5}, {%6,%7}, {%0,%1};"
        : "+r"(d[0]), "+r"(d[1])
        : "r"(a[0]), "r"(a[1]), "r"(a[2]), "r"(a[3]), "r"(b0), "r"(b1));
}

__device__ __forceinline__ void split2h(float v, fp16& h, fp16& l) {
    h = __float2half_rn(v);
    l = __float2half_rn(v - __half2float(h));
}

// ---------------------------------------------------------------------------
// 3-pass split-fp16 GEMM: C[M,N] = A[M,K] @ B[N,K]^T (fp32 effective)
// Single-barrier mainloop: wait -> sync -> prefetch(c+2) -> mma.
// ---------------------------------------------------------------------------
#define TILE_B   16384u
#define STG3_B   (4u * TILE_B)
#define SMEM3    (3u * STG3_B)    // 192 KB
#define NTH      512

__global__ __launch_bounds__(NTH, 1)
void gemm3p(const fp16* __restrict__ Ah_, const fp16* __restrict__ Al_,
            const fp16* __restrict__ Bh_, const fp16* __restrict__ Bl_,
            fp16* __restrict__ Ch, fp16* __restrict__ Cl,
            int M, int N, int K)
{
    extern __shared__ char smem_raw[];
    const uint32_t sbase = smem_to_u32(smem_raw);

    const int tid  = threadIdx.x;
    const int w    = tid >> 5;
    const int lane = tid & 31;
    const int bx = blockIdx.x, by = blockIdx.y;
    const int wm = (w >> 2) * 32;
    const int wn = (w & 3) * 32;

    const fp16* gAh = Ah_ + (size_t)by * 128 * K;
    const fp16* gAl = Al_ + (size_t)by * 128 * K;
    const fp16* gBh = Bh_ + (size_t)bx * 128 * K;
    const fp16* gBl = Bl_ + (size_t)bx * 128 * K;

    float acc[2][4][4];
#pragma unroll
    for (int i = 0; i < 2; i++)
#pragma unroll
        for (int j = 0; j < 4; j++)
#pragma unroll
            for (int k = 0; k < 4; k++) acc[i][j][k] = 0.0f;

    uint32_t lso[2];
    size_t lgo[2];
#pragma unroll
    for (int i = 0; i < 2; i++) {
        int idx = tid + i * NTH;
        int row = idx >> 3;
        int u   = idx & 7;
        lso[i] = (uint32_t)row * 128u + (uint32_t)((u ^ (row & 7)) << 4);
        lgo[i] = (size_t)row * K + (size_t)u * 8;
    }

    const int NC = K >> 6;

    auto load_stage = [&](int c, int s) {
        const size_t kofs = (size_t)c << 6;
        const uint32_t sb = sbase + (uint32_t)s * STG3_B;
#pragma unroll
        for (int i = 0; i < 2; i++) {
            cp_async16(sb + 0u * TILE_B + lso[i], gAh + lgo[i] + kofs);
            cp_async16(sb + 1u * TILE_B + lso[i], gAl + lgo[i] + kofs);
            cp_async16(sb + 2u * TILE_B + lso[i], gBh + lgo[i] + kofs);
            cp_async16(sb + 3u * TILE_B + lso[i], gBl + lgo[i] + kofs);
        }
    };

    load_stage(0, 0); CP_COMMIT();
    if (NC > 1) load_stage(1, 1);
    CP_COMMIT();

    const int lr = lane & 15;
    const int lu = lane >> 4;

    for (int c = 0; c < NC; c++) {
        CP_WAIT(1);
        __syncthreads();

        if (c + 2 < NC) load_stage(c + 2, (c + 2) % 3);
        CP_COMMIT();

        const uint32_t st  = sbase + (uint32_t)(c % 3) * STG3_B;
        const uint32_t Ahb = st;
        const uint32_t Alb = st + 1u * TILE_B;
        const uint32_t Bhb = st + 2u * TILE_B;
        const uint32_t Blb = st + 3u * TILE_B;

#pragma unroll
        for (int ks = 0; ks < 4; ks++) {
            uint32_t ah[2][4], al[2][4], bh[2][4], bl[2][4];
            const int unit = ks * 2 + lu;
#pragma unroll
            for (int mt = 0; mt < 2; mt++) {
                int row = wm + mt * 16 + lr;
                uint32_t off = (uint32_t)row * 128u
                             + (uint32_t)((unit ^ (row & 7)) << 4);
                ldmx4(ah[mt], Ahb + off);
                ldmx4(al[mt], Alb + off);
            }
#pragma unroll
            for (int nt = 0; nt < 2; nt++) {
                int row = wn + nt * 16 + lr;
                uint32_t off = (uint32_t)row * 128u
                             + (uint32_t)((unit ^ (row & 7)) << 4);
                ldmx4(bh[nt], Bhb + off);
                ldmx4(bl[nt], Blb + off);
            }
#pragma unroll
            for (int mt = 0; mt < 2; mt++) {
#pragma unroll
                for (int n8 = 0; n8 < 4; n8++) {
                    const int nt = n8 >> 1, sel = n8 & 1;
                    const uint32_t b0h = bh[nt][sel], b1h = bh[nt][sel + 2];
                    const uint32_t b0l = bl[nt][sel], b1l = bl[nt][sel + 2];
                    mma_f16(acc[mt][n8], ah[mt], b0h, b1h);
                    mma_f16(acc[mt][n8], ah[mt], b0l, b1l);
                    mma_f16(acc[mt][n8], al[mt], b0h, b1h);
                }
            }
        }
    }

    const int g  = lane >> 2;
    const int tc = lane & 3;
#pragma unroll
    for (int mt = 0; mt < 2; mt++) {
#pragma unroll
        for (int n8 = 0; n8 < 4; n8++) {
            const int r0 = by * 128 + wm + mt * 16 + g;
            const int r1 = r0 + 8;
            const int col = bx * 128 + wn + n8 * 8 + tc * 2;
            float c0 = acc[mt][n8][0], c1 = acc[mt][n8][1];
            float c2 = acc[mt][n8][2], c3 = acc[mt][n8][3];
            fp16 h0,l0,h1,l1,h2,l2,h3,l3;
            split2h(c0, h0, l0); split2h(c1, h1, l1);
            split2h(c2, h2, l2); split2h(c3, h3, l3);
            *(__half2*)(Ch + (size_t)r0 * N + col) = __halves2half2(h0, h1);
            *(__half2*)(Cl + (size_t)r0 * N + col) = __halves2half2(l0, l1);
            *(__half2*)(Ch + (size_t)r1 * N + col) = __halves2half2(h2, h3);
            *(__half2*)(Cl + (size_t)r1 * N + col) = __halves2half2(l2, l3);
        }
    }
}

// ---------------------------------------------------------------------------
// 1-pass fp16 GEMM with fp16 ACCUMULATION (filter-grade): S16 = fp16(A @ B^T).
// 3-stage single-barrier pipeline, 96 KB smem -> 2 CTAs/SM.
// ---------------------------------------------------------------------------
#define STG1_B (2u * TILE_B)
#define SMEM1  (3u * STG1_B)     // 96 KB

__global__ __launch_bounds__(NTH, 2)
void gemm1p(const fp16* __restrict__ Ah_, const fp16* __restrict__ Bh_,
            fp16* __restrict__ S16, int M, int N, int K)
{
    extern __shared__ char smem_raw[];
    const uint32_t sbase = smem_to_u32(smem_raw);

    const int tid  = threadIdx.x;
    const int w    = tid >> 5;
    const int lane = tid & 31;
    const int bx = blockIdx.x, by = blockIdx.y;
    const int wm = (w >> 2) * 32;
    const int wn = (w & 3) * 32;

    const fp16* gAh = Ah_ + (size_t)by * 128 * K;
    const fp16* gBh = Bh_ + (size_t)bx * 128 * K;

    uint32_t acc[2][4][2];
#pragma unroll
    for (int i = 0; i < 2; i++)
#pragma unroll
        for (int j = 0; j < 4; j++) {
            acc[i][j][0] = 0u;
            acc[i][j][1] = 0u;
        }

    uint32_t lso[2];
    size_t lgo[2];
#pragma unroll
    for (int i = 0; i < 2; i++) {
        int idx = tid + i * NTH;
        int row = idx >> 3;
        int u   = idx & 7;
        lso[i] = (uint32_t)row * 128u + (uint32_t)((u ^ (row & 7)) << 4);
        lgo[i] = (size_t)row * K + (size_t)u * 8;
    }

    const int NC = K >> 6;

    auto load_stage = [&](int c, int s) {
        const size_t kofs = (size_t)c << 6;
        const uint32_t sb = sbase + (uint32_t)s * STG1_B;
#pragma unroll
        for (int i = 0; i < 2; i++) {
            cp_async16(sb + 0u * TILE_B + lso[i], gAh + lgo[i] + kofs);
            cp_async16(sb + 1u * TILE_B + lso[i], gBh + lgo[i] + kofs);
        }
    };

    load_stage(0, 0); CP_COMMIT();
    if (NC > 1) load_stage(1, 1);
    CP_COMMIT();

    const int lr = lane & 15;
    const int lu = lane >> 4;

    for (int c = 0; c < NC; c++) {
        CP_WAIT(1);
        __syncthreads();

        if (c + 2 < NC) load_stage(c + 2, (c + 2) % 3);
        CP_COMMIT();

        const uint32_t st  = sbase + (uint32_t)(c % 3) * STG1_B;
        const uint32_t Ahb = st;
        const uint32_t Bhb = st + 1u * TILE_B;

#pragma unroll
        for (int ks = 0; ks < 4; ks++) {
            uint32_t ah[2][4], bh[2][4];
            const int unit = ks * 2 + lu;
#pragma unroll
            for (int mt = 0; mt < 2; mt++) {
                int row = wm + mt * 16 + lr;
                uint32_t off = (uint32_t)row * 128u
                             + (uint32_t)((unit ^ (row & 7)) << 4);
                ldmx4(ah[mt], Ahb + off);
            }
#pragma unroll
            for (int nt = 0; nt < 2; nt++) {
                int row = wn + nt * 16 + lr;
                uint32_t off = (uint32_t)row * 128u
                             + (uint32_t)((unit ^ (row & 7)) << 4);
                ldmx4(bh[nt], Bhb + off);
            }
#pragma unroll
            for (int mt = 0; mt < 2; mt++) {
#pragma unroll
                for (int n8 = 0; n8 < 4; n8++) {
                    const int nt = n8 >> 1, sel = n8 & 1;
                    mma_f16a(acc[mt][n8], ah[mt], bh[nt][sel], bh[nt][sel + 2]);
                }
            }
        }
    }

    const int g  = lane >> 2;
    const int tc = lane & 3;
#pragma unroll
    for (int mt = 0; mt < 2; mt++) {
#pragma unroll
        for (int n8 = 0; n8 < 4; n8++) {
            const int r0 = by * 128 + wm + mt * 16 + g;
            const int r1 = r0 + 8;
            const int col = bx * 128 + wn + n8 * 8 + tc * 2;
            *(uint32_t*)(S16 + (size_t)r0 * N + col) = acc[mt][n8][0];
            *(uint32_t*)(S16 + (size_t)r1 * N + col) = acc[mt][n8][1];
        }
    }
}

// ---------------------------------------------------------------------------
// fp32 -> (hi, lo) fp16 split
// ---------------------------------------------------------------------------
__global__ __launch_bounds__(256)
void split_h(const float* __restrict__ in, fp16* __restrict__ oh,
             fp16* __restrict__ ol, int n4)
{
    int i = blockIdx.x * blockDim.x + threadIdx.x;
    if (i >= n4) return;
    float4 v = ((const float4*)in)[i];
    fp16 h0,l0,h1,l1,h2,l2,h3,l3;
    split2h(v.x, h0, l0); split2h(v.y, h1, l1);
    split2h(v.z, h2, l2); split2h(v.w, h3, l3);
    __half2 ha = __halves2half2(h0, h1), hb = __halves2half2(h2, h3);
    __half2 la = __halves2half2(l0, l1), lb = __halves2half2(l2, l3);
    uint2 hu; hu.x = *(uint32_t*)&ha; hu.y = *(uint32_t*)&hb;
    uint2 lu; lu.x = *(uint32_t*)&la; lu.y = *(uint32_t*)&lb;
    ((uint2*)oh)[i] = hu;
    ((uint2*)ol)[i] = lu;
}

// ---------------------------------------------------------------------------
// in [R, C] fp32 -> out [C, R] fp16 (hi, lo) split
// ---------------------------------------------------------------------------
__global__ __launch_bounds__(256)
void transpose_split_h(const float* __restrict__ in, fp16* __restrict__ oh,
                       fp16* __restrict__ ol, int R, int C)
{
    __shared__ float t[32][33];
    const int c0 = blockIdx.x * 32;
    const int r0 = blockIdx.y * 32;
    const int tx = threadIdx.x;
    const int ty = threadIdx.y;
#pragma unroll
    for (int j = 0; j < 32; j += 8)
        t[ty + j][tx] = in[(size_t)(r0 + ty + j) * C + c0 + tx];
    __syncthreads();
#pragma unroll
    for (int j = 0; j < 32; j += 8) {
        float v = t[tx][ty + j];
        fp16 h, l;
        split2h(v, h, l);
        size_t o = (size_t)(c0 + ty + j) * R + r0 + tx;
        oh[o] = h;
        ol[o] = l;
    }
}

// ---------------------------------------------------------------------------
// wvec 2-stage, MLP-rich: 256 blocks (4 e-chunks x 64 a-chunks), 16 a-rows
// per thread (unrolled), fully coalesced; then 64-way reduce. Deterministic.
// ---------------------------------------------------------------------------
__global__ __launch_bounds__(256)
void wvec_part2(const float* __restrict__ Wk, const float* __restrict__ bq,
                float* __restrict__ wp)
{
    const int e = blockIdx.x * 256 + threadIdx.x;
    const int p = blockIdx.y;           // 0..63
    const int a0 = p * 16;
    float s = 0.0f;
#pragma unroll
    for (int i = 0; i < 16; i++)
        s += bq[a0 + i] * Wk[(size_t)(a0 + i) * DIM + e];
    wp[(size_t)p * DIM + e] = s;
}

__global__ __launch_bounds__(256)
void wvec_red2(const float* __restrict__ wp, float* __restrict__ w)
{
    const int e = blockIdx.x * 256 + threadIdx.x;
    float s = 0.0f;
#pragma unroll
    for (int p = 0; p < 64; p++)
        s += wp[(size_t)p * DIM + e];
    w[e] = s;
}

// ---------------------------------------------------------------------------
// v[i] = sum_d x[i, d] * w[d]
// ---------------------------------------------------------------------------
__global__ __launch_bounds__(256)
void vvec(const float* __restrict__ x, const float* __restrict__ w,
          float* __restrict__ v)
{
    const int wid = threadIdx.x >> 5;
    const int lane = threadIdx.x & 31;
    const int row = blockIdx.x * 8 + wid;
    const float* xr = x + (size_t)row * DIM;
    float s = 0.0f;
#pragma unroll
    for (int it = 0; it < 8; it++) {
        int d = (it * 32 + lane) * 4;
        float4 a = *(const float4*)(xr + d);
        float4 b = *(const float4*)(w + d);
        s += a.x * b.x + a.y * b.y + a.z * b.z + a.w * b.w;
    }
#pragma unroll
    for (int o = 16; o > 0; o >>= 1)
        s += __shfl_xor_sync(0xffffffffu, s, o);
    if (lane == 0) v[row] = s;
}

// ---------------------------------------------------------------------------
// Fused per-row (256 threads): fp16 approx logits (S + v) -> threshold
// candidates -> exact fp32 rescore -> softmax -> out[row] = sum w_c * x[c].
// ---------------------------------------------------------------------------
#define CAP    1024
#define MARGIN 24.5f

__global__ __launch_bounds__(256, 2)
void fused_attn_out(const fp16* __restrict__ S, const float* __restrict__ vcol,
                    const fp16* __restrict__ th_, const fp16* __restrict__ tl_,
                    const float* __restrict__ x, float* __restrict__ out)
{
    const int row  = blockIdx.x;
    const int tid  = threadIdx.x;
    const int lane = tid & 31;
    const int wid  = tid >> 5;

    __shared__ __align__(16) float t_row[DIM];
    __shared__ int   cidx[CAP];
    __shared__ float cval[CAP];
    __shared__ float redF[8];
    __shared__ int   redI[16];
    __shared__ int   s_cnt;
    __shared__ float s_bcast;

    {
        uint2 uh = ((const uint2*)(th_ + (size_t)row * DIM))[tid];
        uint2 ul = ((const uint2*)(tl_ + (size_t)row * DIM))[tid];
        __half2 h0 = *(__half2*)&uh.x, h1 = *(__half2*)&uh.y;
        __half2 l0 = *(__half2*)&ul.x, l1 = *(__half2*)&ul.y;
        float4 tv;
        tv.x = __low2float(h0)  + __low2float(l0);
        tv.y = __high2float(h0) + __high2float(l0);
        tv.z = __low2float(h1)  + __low2float(l1);
        tv.w = __high2float(h1) + __high2float(l1);
        *(float4*)(&t_row[tid * 4]) = tv;
    }

    const fp16* Sr = S + (size_t)row * N_TOK;
    float l[4][4];
    float mx = -CUDART_INF_F;
#pragma unroll
    for (int i = 0; i < 4; i++) {
        size_t p = (size_t)(tid + i * 256) * 4;
        uint2 u = *(const uint2*)(Sr + p);
        __half2 h0 = *(__half2*)&u.x, h1 = *(__half2*)&u.y;
        float4 vv = *(const float4*)(vcol + p);
        l[i][0] = __low2float(h0)  + vv.x;
        l[i][1] = __high2float(h0) + vv.y;
        l[i][2] = __low2float(h1)  + vv.z;
        l[i][3] = __high2float(h1) + vv.w;
#pragma unroll
        for (int e = 0; e < 4; e++) mx = fmaxf(mx, l[i][e]);
    }
#pragma unroll
    for (int o = 16; o > 0; o >>= 1)
        mx = fmaxf(mx, __shfl_xor_sync(0xffffffffu, mx, o));
    if (lane == 0) redF[wid] = mx;
    __syncthreads();
    if (wid == 0) {
        float m = (lane < 8) ? redF[lane] : -CUDART_INF_F;
#pragma unroll
        for (int o = 4; o > 0; o >>= 1)
            m = fmaxf(m, __shfl_xor_sync(0xffffffffu, m, o));
        if (lane == 0) s_bcast = m;
    }
    __syncthreads();
    const float thr = s_bcast - MARGIN;

    int mycnt = 0;
#pragma unroll
    for (int i = 0; i < 4; i++)
#pragma unroll
        for (int e = 0; e < 4; e++)
            if (l[i][e] > thr) mycnt++;

    int inc = mycnt;
#pragma unroll
    for (int o = 1; o < 32; o <<= 1) {
        int n = __shfl_up_sync(0xffffffffu, inc, o);
        if (lane >= o) inc += n;
    }
    const int myoff_w = inc - mycnt;
    const int wtot = __shfl_sync(0xffffffffu, inc, 31);
    if (lane == 0) redI[wid] = wtot;
    __syncthreads();
    if (wid == 0 && lane < 8) {
        int v = redI[lane];
#pragma unroll
        for (int o = 1; o < 8; o <<= 1) {
            int n = __shfl_up_sync(0x000000ffu, v, o);
            if (lane >= o) v += n;
        }
        redI[8 + lane] = v - redI[lane];
        if (lane == 7) s_cnt = (v > CAP) ? CAP : v;
    }
    __syncthreads();

    int k = redI[8 + wid] + myoff_w;
#pragma unroll
    for (int i = 0; i < 4; i++) {
#pragma unroll
        for (int e = 0; e < 4; e++) {
            if (l[i][e] > thr) {
                if (k < CAP) cidx[k] = (tid + i * 256) * 4 + e;
                k++;
            }
        }
    }
    __syncthreads();

    const int cnt = s_cnt;

    for (int c = wid; c < cnt; c += 8) {
        const float* xj = x + (size_t)cidx[c] * DIM;
        float s = 0.0f;
#pragma unroll
        for (int it = 0; it < 8; it++) {
            int d = (it * 32 + lane) * 4;
            float4 a = *(const float4*)(&t_row[d]);
            float4 b = *(const float4*)(xj + d);
            s += a.x * b.x + a.y * b.y + a.z * b.z + a.w * b.w;
        }
#pragma unroll
        for (int o = 16; o > 0; o >>= 1)
            s += __shfl_xor_sync(0xffffffffu, s, o);
        if (lane == 0) cval[c] = s + vcol[cidx[c]];
    }
    __syncthreads();

    float m2 = -CUDART_INF_F;
    for (int c = tid; c < cnt; c += 256) m2 = fmaxf(m2, cval[c]);
#pragma unroll
    for (int o = 16; o > 0; o >>= 1)
        m2 = fmaxf(m2, __shfl_xor_sync(0xffffffffu, m2, o));
    if (lane == 0) redF[wid] = m2;
    __syncthreads();
    if (wid == 0) {
        float m = (lane < 8) ? redF[lane] : -CUDART_INF_F;
#pragma unroll
        for (int o = 4; o > 0; o >>= 1)
            m = fmaxf(m, __shfl_xor_sync(0xffffffffu, m, o));
        if (lane == 0) s_bcast = m;
    }
    __syncthreads();
    m2 = s_bcast;
    __syncthreads();

    float sum = 0.0f;
    for (int c = tid; c < cnt; c += 256) {
        float e = __expf(cval[c] - m2);
        cval[c] = e;
        sum += e;
    }
#pragma unroll
    for (int o = 16; o > 0; o >>= 1)
        sum += __shfl_xor_sync(0xffffffffu, sum, o);
    if (lane == 0) redF[wid] = sum;
    __syncthreads();
    if (wid == 0) {
        float s = (lane < 8) ? redF[lane] : 0.0f;
#pragma unroll
        for (int o = 4; o > 0; o >>= 1)
            s += __shfl_xor_sync(0xffffffffu, s, o);
        if (lane == 0) s_bcast = s;
    }
    __syncthreads();
    const float inv = 1.0f / s_bcast;

    float4 acc; acc.x = 0.0f; acc.y = 0.0f; acc.z = 0.0f; acc.w = 0.0f;
    const int col = tid * 4;
    for (int c = 0; c < cnt; c++) {
        const float wc = cval[c] * inv;
        float4 xv = *(const float4*)(x + (size_t)cidx[c] * DIM + col);
        acc.x += wc * xv.x; acc.y += wc * xv.y;
        acc.z += wc * xv.z; acc.w += wc * xv.w;
    }
    *(float4*)(out + (size_t)row * DIM + col) = acc;
}

// ---------------------------------------------------------------------------
// Launch
// ---------------------------------------------------------------------------
extern "C" void kernel_launch(void* const* d_in, const int* in_sizes, int n_in,
                              void* d_out, int out_size)
{
    const float* x  = (const float*)d_in[0];
    const float* Wq = (const float*)d_in[1];
    const float* bq = (const float*)d_in[2];
    const float* Wk = (const float*)d_in[3];
    const float* bk = (const float*)d_in[4];   // cancels in softmax
    float* out = (float*)d_out;
    (void)bk;

    fp16 *xh, *xl, *wqt, *wqtl, *wkt, *wktl, *mth, *mtl, *th, *tl, *s16;
    float *wp, *wv, *vv;
    cudaGetSymbolAddress((void**)&xh,   g_xh);
    cudaGetSymbolAddress((void**)&xl,   g_xl);
    cudaGetSymbolAddress((void**)&wqt,  g_wqt);
    cudaGetSymbolAddress((void**)&wqtl, g_wqtl);
    cudaGetSymbolAddress((void**)&wkt,  g_wkt);
    cudaGetSymbolAddress((void**)&wktl, g_wktl);
    cudaGetSymbolAddress((void**)&mth,  g_mth);
    cudaGetSymbolAddress((void**)&mtl,  g_mtl);
    cudaGetSymbolAddress((void**)&th,   g_th);
    cudaGetSymbolAddress((void**)&tl,   g_tl);
    cudaGetSymbolAddress((void**)&s16,  g_s16);
    cudaGetSymbolAddress((void**)&wp,   g_wp);
    cudaGetSymbolAddress((void**)&wv,   g_w);
    cudaGetSymbolAddress((void**)&vv,   g_v);

    cudaFuncSetAttribute(gemm3p, cudaFuncAttributeMaxDynamicSharedMemorySize, SMEM3);
    cudaFuncSetAttribute(gemm1p, cudaFuncAttributeMaxDynamicSharedMemorySize, SMEM1);

    // Prep
    {
        int n4 = N_TOK * DIM / 4;
        split_h<<<(n4 + 255) / 256, 256>>>(x, xh, xl, n4);
        transpose_split_h<<<dim3(DIM / 32, DIM / 32), dim3(32, 8)>>>(Wq, wqt, wqtl, DIM, DIM);
        transpose_split_h<<<dim3(DIM / 32, DIM / 32), dim3(32, 8)>>>(Wk, wkt, wktl, DIM, DIM);
        wvec_part2<<<dim3(DIM / 256, 64), 256>>>(Wk, bq, wp);
        wvec_red2<<<DIM / 256, 256>>>(wp, wv);
        vvec<<<N_TOK / 8, 256>>>(x, wv, vv);
    }

    // Mt = Wk^T @ Wq, split out. M=N=K=1024
    gemm3p<<<dim3(DIM / 128, DIM / 128), NTH, SMEM3>>>(
        wkt, wktl, wqt, wqtl, mth, mtl, DIM, DIM, DIM);

    // t = x @ M, split out. M=4096,N=1024,K=1024
    gemm3p<<<dim3(DIM / 128, N_TOK / 128), NTH, SMEM3>>>(
        xh, xl, mth, mtl, th, tl, N_TOK, DIM, DIM);

    // approx scores = th @ xh^T (1-pass, fp16 accumulate, occ-2), fp16 out
    gemm1p<<<dim3(N_TOK / 128, N_TOK / 128), NTH, SMEM1>>>(
        th, xh, s16, N_TOK, N_TOK, DIM);

    // fused: candidates, exact rescore, softmax, sparse output
    fused_attn_out<<<N_TOK, 256>>>(s16, vv, th, tl, x, out);
}

// round 16
// speedup vs baseline: 1.0128x; 1.0128x over previous
#include <cuda_runtime.h>
#include <cuda_fp16.h>
#include <math_constants.h>
#include <cstdint>

#define N_TOK 4096
#define DIM   1024

typedef __half fp16;

// ---------------------------------------------------------------------------
// Scratch (device globals; no allocation allowed)
// ---------------------------------------------------------------------------
__device__ fp16  g_xh [(size_t)N_TOK * DIM];
__device__ fp16  g_xl [(size_t)N_TOK * DIM];
__device__ fp16  g_wqt[(size_t)DIM * DIM];
__device__ fp16  g_wqtl[(size_t)DIM * DIM];
__device__ fp16  g_wkt[(size_t)DIM * DIM];
__device__ fp16  g_wktl[(size_t)DIM * DIM];
__device__ fp16  g_mth[(size_t)DIM * DIM];
__device__ fp16  g_mtl[(size_t)DIM * DIM];
__device__ fp16  g_th [(size_t)N_TOK * DIM];
__device__ fp16  g_tl [(size_t)N_TOK * DIM];
__device__ fp16  g_s16[(size_t)N_TOK * N_TOK];  // approx scores (fp16)
__device__ float g_wp [64 * DIM];                // wvec partials
__device__ float g_w  [DIM];
__device__ float g_v  [N_TOK];

// ---------------------------------------------------------------------------
// Helpers
// ---------------------------------------------------------------------------
__device__ __forceinline__ uint32_t smem_to_u32(const void* p) {
    uint32_t a;
    asm("{ .reg .u64 t; cvta.to.shared.u64 t, %1; cvt.u32.u64 %0, t; }"
        : "=r"(a) : "l"(p));
    return a;
}

__device__ __forceinline__ void cp_async16(uint32_t dst, const void* src) {
    asm volatile("cp.async.cg.shared.global [%0], [%1], 16;"
        :: "r"(dst), "l"(src) : "memory");
}
#define CP_COMMIT() asm volatile("cp.async.commit_group;" ::: "memory")
#define CP_WAIT(n)  asm volatile("cp.async.wait_group %0;" :: "n"(n) : "memory")

__device__ __forceinline__ void ldmx4(uint32_t r[4], uint32_t addr) {
    asm volatile("ldmatrix.sync.aligned.m8n8.x4.shared.b16 {%0,%1,%2,%3}, [%4];"
        : "=r"(r[0]), "=r"(r[1]), "=r"(r[2]), "=r"(r[3]) : "r"(addr));
}

__device__ __forceinline__ void mma_f16(float d[4], const uint32_t a[4],
                                        uint32_t b0, uint32_t b1) {
    asm volatile(
        "mma.sync.aligned.m16n8k16.row.col.f32.f16.f16.f32 "
        "{%0,%1,%2,%3}, {%4,%5,%6,%7}, {%8,%9}, {%0,%1,%2,%3};"
        : "+f"(d[0]), "+f"(d[1]), "+f"(d[2]), "+f"(d[3])
        : "r"(a[0]), "r"(a[1]), "r"(a[2]), "r"(a[3]), "r"(b0), "r"(b1));
}

// fp16-accumulator HMMA (filter-grade)
__device__ __forceinline__ void mma_f16a(uint32_t d[2], const uint32_t a[4],
                                         uint32_t b0, uint32_t b1) {
    asm volatile(
        "mma.sync.aligned.m16n8k16.row.col.f16.f16.f16.f16 "
        "{%0,%1}, {%2,%3,%4,%5}, {%6,%7}, {%0,%1};"
        : "+r"(d[0]), "+r"(d[1])
        : "r"(a[0]), "r"(a[1]), "r"(a[2]), "r"(a[3]), "r"(b0), "r"(b1));
}

__device__ __forceinline__ void split2h(float v, fp16& h, fp16& l) {
    h = __float2half_rn(v);
    l = __float2half_rn(v - __half2float(h));
}

// ---------------------------------------------------------------------------
// 3-pass split-fp16 GEMM: C[M,N] = A[M,K] @ B[N,K]^T (fp32 effective)
// Single-barrier mainloop: wait -> sync -> prefetch(c+2) -> mma.
// ---------------------------------------------------------------------------
#define TILE_B   16384u
#define STG3_B   (4u * TILE_B)
#define SMEM3    (3u * STG3_B)    // 192 KB
#define NTH      512

__global__ __launch_bounds__(NTH, 1)
void gemm3p(const fp16* __restrict__ Ah_, const fp16* __restrict__ Al_,
            const fp16* __restrict__ Bh_, const fp16* __restrict__ Bl_,
            fp16* __restrict__ Ch, fp16* __restrict__ Cl,
            int M, int N, int K)
{
    extern __shared__ char smem_raw[];
    const uint32_t sbase = smem_to_u32(smem_raw);

    const int tid  = threadIdx.x;
    const int w    = tid >> 5;
    const int lane = tid & 31;
    const int bx = blockIdx.x, by = blockIdx.y;
    const int wm = (w >> 2) * 32;
    const int wn = (w & 3) * 32;

    const fp16* gAh = Ah_ + (size_t)by * 128 * K;
    const fp16* gAl = Al_ + (size_t)by * 128 * K;
    const fp16* gBh = Bh_ + (size_t)bx * 128 * K;
    const fp16* gBl = Bl_ + (size_t)bx * 128 * K;

    float acc[2][4][4];
#pragma unroll
    for (int i = 0; i < 2; i++)
#pragma unroll
        for (int j = 0; j < 4; j++)
#pragma unroll
            for (int k = 0; k < 4; k++) acc[i][j][k] = 0.0f;

    uint32_t lso[2];
    size_t lgo[2];
#pragma unroll
    for (int i = 0; i < 2; i++) {
        int idx = tid + i * NTH;
        int row = idx >> 3;
        int u   = idx & 7;
        lso[i] = (uint32_t)row * 128u + (uint32_t)((u ^ (row & 7)) << 4);
        lgo[i] = (size_t)row * K + (size_t)u * 8;
    }

    const int NC = K >> 6;

    auto load_stage = [&](int c, int s) {
        const size_t kofs = (size_t)c << 6;
        const uint32_t sb = sbase + (uint32_t)s * STG3_B;
#pragma unroll
        for (int i = 0; i < 2; i++) {
            cp_async16(sb + 0u * TILE_B + lso[i], gAh + lgo[i] + kofs);
            cp_async16(sb + 1u * TILE_B + lso[i], gAl + lgo[i] + kofs);
            cp_async16(sb + 2u * TILE_B + lso[i], gBh + lgo[i] + kofs);
            cp_async16(sb + 3u * TILE_B + lso[i], gBl + lgo[i] + kofs);
        }
    };

    load_stage(0, 0); CP_COMMIT();
    if (NC > 1) load_stage(1, 1);
    CP_COMMIT();

    const int lr = lane & 15;
    const int lu = lane >> 4;

    for (int c = 0; c < NC; c++) {
        CP_WAIT(1);
        __syncthreads();

        if (c + 2 < NC) load_stage(c + 2, (c + 2) % 3);
        CP_COMMIT();

        const uint32_t st  = sbase + (uint32_t)(c % 3) * STG3_B;
        const uint32_t Ahb = st;
        const uint32_t Alb = st + 1u * TILE_B;
        const uint32_t Bhb = st + 2u * TILE_B;
        const uint32_t Blb = st + 3u * TILE_B;

#pragma unroll
        for (int ks = 0; ks < 4; ks++) {
            uint32_t ah[2][4], al[2][4], bh[2][4], bl[2][4];
            const int unit = ks * 2 + lu;
#pragma unroll
            for (int mt = 0; mt < 2; mt++) {
                int row = wm + mt * 16 + lr;
                uint32_t off = (uint32_t)row * 128u
                             + (uint32_t)((unit ^ (row & 7)) << 4);
                ldmx4(ah[mt], Ahb + off);
                ldmx4(al[mt], Alb + off);
            }
#pragma unroll
            for (int nt = 0; nt < 2; nt++) {
                int row = wn + nt * 16 + lr;
                uint32_t off = (uint32_t)row * 128u
                             + (uint32_t)((unit ^ (row & 7)) << 4);
                ldmx4(bh[nt], Bhb + off);
                ldmx4(bl[nt], Blb + off);
            }
#pragma unroll
            for (int mt = 0; mt < 2; mt++) {
#pragma unroll
                for (int n8 = 0; n8 < 4; n8++) {
                    const int nt = n8 >> 1, sel = n8 & 1;
                    const uint32_t b0h = bh[nt][sel], b1h = bh[nt][sel + 2];
                    const uint32_t b0l = bl[nt][sel], b1l = bl[nt][sel + 2];
                    mma_f16(acc[mt][n8], ah[mt], b0h, b1h);
                    mma_f16(acc[mt][n8], ah[mt], b0l, b1l);
                    mma_f16(acc[mt][n8], al[mt], b0h, b1h);
                }
            }
        }
    }

    const int g  = lane >> 2;
    const int tc = lane & 3;
#pragma unroll
    for (int mt = 0; mt < 2; mt++) {
#pragma unroll
        for (int n8 = 0; n8 < 4; n8++) {
            const int r0 = by * 128 + wm + mt * 16 + g;
            const int r1 = r0 + 8;
            const int col = bx * 128 + wn + n8 * 8 + tc * 2;
            float c0 = acc[mt][n8][0], c1 = acc[mt][n8][1];
            float c2 = acc[mt][n8][2], c3 = acc[mt][n8][3];
            fp16 h0,l0,h1,l1,h2,l2,h3,l3;
            split2h(c0, h0, l0); split2h(c1, h1, l1);
            split2h(c2, h2, l2); split2h(c3, h3, l3);
            *(__half2*)(Ch + (size_t)r0 * N + col) = __halves2half2(h0, h1);
            *(__half2*)(Cl + (size_t)r0 * N + col) = __halves2half2(l0, l1);
            *(__half2*)(Ch + (size_t)r1 * N + col) = __halves2half2(h2, h3);
            *(__half2*)(Cl + (size_t)r1 * N + col) = __halves2half2(l2, l3);
        }
    }
}

// ---------------------------------------------------------------------------
// 1-pass fp16 GEMM with fp16 ACCUMULATION (filter-grade): S16 = fp16(A @ B^T).
// 3-stage single-barrier pipeline, 96 KB smem -> 2 CTAs/SM.
// ---------------------------------------------------------------------------
#define STG1_B (2u * TILE_B)
#define SMEM1  (3u * STG1_B)     // 96 KB

__global__ __launch_bounds__(NTH, 2)
void gemm1p(const fp16* __restrict__ Ah_, const fp16* __restrict__ Bh_,
            fp16* __restrict__ S16, int M, int N, int K)
{
    extern __shared__ char smem_raw[];
    const uint32_t sbase = smem_to_u32(smem_raw);

    const int tid  = threadIdx.x;
    const int w    = tid >> 5;
    const int lane = tid & 31;
    const int bx = blockIdx.x, by = blockIdx.y;
    const int wm = (w >> 2) * 32;
    const int wn = (w & 3) * 32;

    const fp16* gAh = Ah_ + (size_t)by * 128 * K;
    const fp16* gBh = Bh_ + (size_t)bx * 128 * K;

    uint32_t acc[2][4][2];
#pragma unroll
    for (int i = 0; i < 2; i++)
#pragma unroll
        for (int j = 0; j < 4; j++) {
            acc[i][j][0] = 0u;
            acc[i][j][1] = 0u;
        }

    uint32_t lso[2];
    size_t lgo[2];
#pragma unroll
    for (int i = 0; i < 2; i++) {
        int idx = tid + i * NTH;
        int row = idx >> 3;
        int u   = idx & 7;
        lso[i] = (uint32_t)row * 128u + (uint32_t)((u ^ (row & 7)) << 4);
        lgo[i] = (size_t)row * K + (size_t)u * 8;
    }

    const int NC = K >> 6;

    auto load_stage = [&](int c, int s) {
        const size_t kofs = (size_t)c << 6;
        const uint32_t sb = sbase + (uint32_t)s * STG1_B;
#pragma unroll
        for (int i = 0; i < 2; i++) {
            cp_async16(sb + 0u * TILE_B + lso[i], gAh + lgo[i] + kofs);
            cp_async16(sb + 1u * TILE_B + lso[i], gBh + lgo[i] + kofs);
        }
    };

    load_stage(0, 0); CP_COMMIT();
    if (NC > 1) load_stage(1, 1);
    CP_COMMIT();

    const int lr = lane & 15;
    const int lu = lane >> 4;

    for (int c = 0; c < NC; c++) {
        CP_WAIT(1);
        __syncthreads();

        if (c + 2 < NC) load_stage(c + 2, (c + 2) % 3);
        CP_COMMIT();

        const uint32_t st  = sbase + (uint32_t)(c % 3) * STG1_B;
        const uint32_t Ahb = st;
        const uint32_t Bhb = st + 1u * TILE_B;

#pragma unroll
        for (int ks = 0; ks < 4; ks++) {
            uint32_t ah[2][4], bh[2][4];
            const int unit = ks * 2 + lu;
#pragma unroll
            for (int mt = 0; mt < 2; mt++) {
                int row = wm + mt * 16 + lr;
                uint32_t off = (uint32_t)row * 128u
                             + (uint32_t)((unit ^ (row & 7)) << 4);
                ldmx4(ah[mt], Ahb + off);
            }
#pragma unroll
            for (int nt = 0; nt < 2; nt++) {
                int row = wn + nt * 16 + lr;
                uint32_t off = (uint32_t)row * 128u
                             + (uint32_t)((unit ^ (row & 7)) << 4);
                ldmx4(bh[nt], Bhb + off);
            }
#pragma unroll
            for (int mt = 0; mt < 2; mt++) {
#pragma unroll
                for (int n8 = 0; n8 < 4; n8++) {
                    const int nt = n8 >> 1, sel = n8 & 1;
                    mma_f16a(acc[mt][n8], ah[mt], bh[nt][sel], bh[nt][sel + 2]);
                }
            }
        }
    }

    const int g  = lane >> 2;
    const int tc = lane & 3;
#pragma unroll
    for (int mt = 0; mt < 2; mt++) {
#pragma unroll
        for (int n8 = 0; n8 < 4; n8++) {
            const int r0 = by * 128 + wm + mt * 16 + g;
            const int r1 = r0 + 8;
            const int col = bx * 128 + wn + n8 * 8 + tc * 2;
            *(uint32_t*)(S16 + (size_t)r0 * N + col) = acc[mt][n8][0];
            *(uint32_t*)(S16 + (size_t)r1 * N + col) = acc[mt][n8][1];
        }
    }
}

// ---------------------------------------------------------------------------
// Fused: x row -> (hi, lo) fp16 split AND v[row] = x[row] . w
// One block per row, 256 threads, x read exactly once.
// ---------------------------------------------------------------------------
__global__ __launch_bounds__(256)
void split_vvec(const float* __restrict__ x, const float* __restrict__ w,
                fp16* __restrict__ oh, fp16* __restrict__ ol,
                float* __restrict__ v)
{
    __shared__ float red[8];
    const int row = blockIdx.x;
    const int tid = threadIdx.x;
    const int lane = tid & 31;
    const int wid = tid >> 5;

    float4 xv = ((const float4*)(x + (size_t)row * DIM))[tid];
    float4 wv = ((const float4*)w)[tid];

    fp16 h0,l0,h1,l1,h2,l2,h3,l3;
    split2h(xv.x, h0, l0); split2h(xv.y, h1, l1);
    split2h(xv.z, h2, l2); split2h(xv.w, h3, l3);
    __half2 ha = __halves2half2(h0, h1), hb = __halves2half2(h2, h3);
    __half2 la = __halves2half2(l0, l1), lb = __halves2half2(l2, l3);
    uint2 hu; hu.x = *(uint32_t*)&ha; hu.y = *(uint32_t*)&hb;
    uint2 lu; lu.x = *(uint32_t*)&la; lu.y = *(uint32_t*)&lb;
    ((uint2*)(oh + (size_t)row * DIM))[tid] = hu;
    ((uint2*)(ol + (size_t)row * DIM))[tid] = lu;

    float s = xv.x * wv.x + xv.y * wv.y + xv.z * wv.z + xv.w * wv.w;
#pragma unroll
    for (int o = 16; o > 0; o >>= 1)
        s += __shfl_xor_sync(0xffffffffu, s, o);
    if (lane == 0) red[wid] = s;
    __syncthreads();
    if (wid == 0) {
        float t = (lane < 8) ? red[lane] : 0.0f;
#pragma unroll
        for (int o = 4; o > 0; o >>= 1)
            t += __shfl_xor_sync(0xffffffffu, t, o);
        if (lane == 0) v[row] = t;
    }
}

// ---------------------------------------------------------------------------
// Both W transposes in one launch: z=0 -> Wq, z=1 -> Wk.
// in [DIM, DIM] fp32 -> out [DIM, DIM] fp16 (hi, lo) split, transposed.
// ---------------------------------------------------------------------------
__global__ __launch_bounds__(256)
void transpose_split_w2(const float* __restrict__ Wq, const float* __restrict__ Wk,
                        fp16* __restrict__ qh, fp16* __restrict__ ql,
                        fp16* __restrict__ kh, fp16* __restrict__ kl)
{
    __shared__ float t[32][33];
    const float* in = blockIdx.z ? Wk : Wq;
    fp16* oh = blockIdx.z ? kh : qh;
    fp16* ol = blockIdx.z ? kl : ql;
    const int c0 = blockIdx.x * 32;
    const int r0 = blockIdx.y * 32;
    const int tx = threadIdx.x;
    const int ty = threadIdx.y;
#pragma unroll
    for (int j = 0; j < 32; j += 8)
        t[ty + j][tx] = in[(size_t)(r0 + ty + j) * DIM + c0 + tx];
    __syncthreads();
#pragma unroll
    for (int j = 0; j < 32; j += 8) {
        float v = t[tx][ty + j];
        fp16 h, l;
        split2h(v, h, l);
        size_t o = (size_t)(c0 + ty + j) * DIM + r0 + tx;
        oh[o] = h;
        ol[o] = l;
    }
}

// ---------------------------------------------------------------------------
// wvec 2-stage, MLP-rich (R15-verified): partials then reduce.
// ---------------------------------------------------------------------------
__global__ __launch_bounds__(256)
void wvec_part2(const float* __restrict__ Wk, const float* __restrict__ bq,
                float* __restrict__ wp)
{
    const int e = blockIdx.x * 256 + threadIdx.x;
    const int p = blockIdx.y;           // 0..63
    const int a0 = p * 16;
    float s = 0.0f;
#pragma unroll
    for (int i = 0; i < 16; i++)
        s += bq[a0 + i] * Wk[(size_t)(a0 + i) * DIM + e];
    wp[(size_t)p * DIM + e] = s;
}

__global__ __launch_bounds__(256)
void wvec_red2(const float* __restrict__ wp, float* __restrict__ w)
{
    const int e = blockIdx.x * 256 + threadIdx.x;
    float s = 0.0f;
#pragma unroll
    for (int p = 0; p < 64; p++)
        s += wp[(size_t)p * DIM + e];
    w[e] = s;
}

// ---------------------------------------------------------------------------
// Fused per-row (256 threads): fp16 approx logits (S + v) -> threshold
// candidates -> exact fp32 rescore -> softmax -> out[row] = sum w_c * x[c].
// ---------------------------------------------------------------------------
#define CAP    1024
#define MARGIN 24.5f

__global__ __launch_bounds__(256, 2)
void fused_attn_out(const fp16* __restrict__ S, const float* __restrict__ vcol,
                    const fp16* __restrict__ th_, const fp16* __restrict__ tl_,
                    const float* __restrict__ x, float* __restrict__ out)
{
    const int row  = blockIdx.x;
    const int tid  = threadIdx.x;
    const int lane = tid & 31;
    const int wid  = tid >> 5;

    __shared__ __align__(16) float t_row[DIM];
    __shared__ int   cidx[CAP];
    __shared__ float cval[CAP];
    __shared__ float redF[8];
    __shared__ int   redI[16];
    __shared__ int   s_cnt;
    __shared__ float s_bcast;

    {
        uint2 uh = ((const uint2*)(th_ + (size_t)row * DIM))[tid];
        uint2 ul = ((const uint2*)(tl_ + (size_t)row * DIM))[tid];
        __half2 h0 = *(__half2*)&uh.x, h1 = *(__half2*)&uh.y;
        __half2 l0 = *(__half2*)&ul.x, l1 = *(__half2*)&ul.y;
        float4 tv;
        tv.x = __low2float(h0)  + __low2float(l0);
        tv.y = __high2float(h0) + __high2float(l0);
        tv.z = __low2float(h1)  + __low2float(l1);
        tv.w = __high2float(h1) + __high2float(l1);
        *(float4*)(&t_row[tid * 4]) = tv;
    }

    const fp16* Sr = S + (size_t)row * N_TOK;
    float l[4][4];
    float mx = -CUDART_INF_F;
#pragma unroll
    for (int i = 0; i < 4; i++) {
        size_t p = (size_t)(tid + i * 256) * 4;
        uint2 u = *(const uint2*)(Sr + p);
        __half2 h0 = *(__half2*)&u.x, h1 = *(__half2*)&u.y;
        float4 vv = *(const float4*)(vcol + p);
        l[i][0] = __low2float(h0)  + vv.x;
        l[i][1] = __high2float(h0) + vv.y;
        l[i][2] = __low2float(h1)  + vv.z;
        l[i][3] = __high2float(h1) + vv.w;
#pragma unroll
        for (int e = 0; e < 4; e++) mx = fmaxf(mx, l[i][e]);
    }
#pragma unroll
    for (int o = 16; o > 0; o >>= 1)
        mx = fmaxf(mx, __shfl_xor_sync(0xffffffffu, mx, o));
    if (lane == 0) redF[wid] = mx;
    __syncthreads();
    if (wid == 0) {
        float m = (lane < 8) ? redF[lane] : -CUDART_INF_F;
#pragma unroll
        for (int o = 4; o > 0; o >>= 1)
            m = fmaxf(m, __shfl_xor_sync(0xffffffffu, m, o));
        if (lane == 0) s_bcast = m;
    }
    __syncthreads();
    const float thr = s_bcast - MARGIN;

    int mycnt = 0;
#pragma unroll
    for (int i = 0; i < 4; i++)
#pragma unroll
        for (int e = 0; e < 4; e++)
            if (l[i][e] > thr) mycnt++;

    int inc = mycnt;
#pragma unroll
    for (int o = 1; o < 32; o <<= 1) {
        int n = __shfl_up_sync(0xffffffffu, inc, o);
        if (lane >= o) inc += n;
    }
    const int myoff_w = inc - mycnt;
    const int wtot = __shfl_sync(0xffffffffu, inc, 31);
    if (lane == 0) redI[wid] = wtot;
    __syncthreads();
    if (wid == 0 && lane < 8) {
        int v = redI[lane];
#pragma unroll
        for (int o = 1; o < 8; o <<= 1) {
            int n = __shfl_up_sync(0x000000ffu, v, o);
            if (lane >= o) v += n;
        }
        redI[8 + lane] = v - redI[lane];
        if (lane == 7) s_cnt = (v > CAP) ? CAP : v;
    }
    __syncthreads();

    int k = redI[8 + wid] + myoff_w;
#pragma unroll
    for (int i = 0; i < 4; i++) {
#pragma unroll
        for (int e = 0; e < 4; e++) {
            if (l[i][e] > thr) {
                if (k < CAP) cidx[k] = (tid + i * 256) * 4 + e;
                k++;
            }
        }
    }
    __syncthreads();

    const int cnt = s_cnt;

    for (int c = wid; c < cnt; c += 8) {
        const float* xj = x + (size_t)cidx[c] * DIM;
        float s = 0.0f;
#pragma unroll
        for (int it = 0; it < 8; it++) {
            int d = (it * 32 + lane) * 4;
            float4 a = *(const float4*)(&t_row[d]);
            float4 b = *(const float4*)(xj + d);
            s += a.x * b.x + a.y * b.y + a.z * b.z + a.w * b.w;
        }
#pragma unroll
        for (int o = 16; o > 0; o >>= 1)
            s += __shfl_xor_sync(0xffffffffu, s, o);
        if (lane == 0) cval[c] = s + vcol[cidx[c]];
    }
    __syncthreads();

    float m2 = -CUDART_INF_F;
    for (int c = tid; c < cnt; c += 256) m2 = fmaxf(m2, cval[c]);
#pragma unroll
    for (int o = 16; o > 0; o >>= 1)
        m2 = fmaxf(m2, __shfl_xor_sync(0xffffffffu, m2, o));
    if (lane == 0) redF[wid] = m2;
    __syncthreads();
    if (wid == 0) {
        float m = (lane < 8) ? redF[lane] : -CUDART_INF_F;
#pragma unroll
        for (int o = 4; o > 0; o >>= 1)
            m = fmaxf(m, __shfl_xor_sync(0xffffffffu, m, o));
        if (lane == 0) s_bcast = m;
    }
    __syncthreads();
    m2 = s_bcast;
    __syncthreads();

    float sum = 0.0f;
    for (int c = tid; c < cnt; c += 256) {
        float e = __expf(cval[c] - m2);
        cval[c] = e;
        sum += e;
    }
#pragma unroll
    for (int o = 16; o > 0; o >>= 1)
        sum += __shfl_xor_sync(0xffffffffu, sum, o);
    if (lane == 0) redF[wid] = sum;
    __syncthreads();
    if (wid == 0) {
        float s = (lane < 8) ? redF[lane] : 0.0f;
#pragma unroll
        for (int o = 4; o > 0; o >>= 1)
            s += __shfl_xor_sync(0xffffffffu, s, o);
        if (lane == 0) s_bcast = s;
    }
    __syncthreads();
    const float inv = 1.0f / s_bcast;

    float4 acc; acc.x = 0.0f; acc.y = 0.0f; acc.z = 0.0f; acc.w = 0.0f;
    const int col = tid * 4;
    for (int c = 0; c < cnt; c++) {
        const float wc = cval[c] * inv;
        float4 xv = *(const float4*)(x + (size_t)cidx[c] * DIM + col);
        acc.x += wc * xv.x; acc.y += wc * xv.y;
        acc.z += wc * xv.z; acc.w += wc * xv.w;
    }
    *(float4*)(out + (size_t)row * DIM + col) = acc;
}

// ---------------------------------------------------------------------------
// Launch
// ---------------------------------------------------------------------------
extern "C" void kernel_launch(void* const* d_in, const int* in_sizes, int n_in,
                              void* d_out, int out_size)
{
    const float* x  = (const float*)d_in[0];
    const float* Wq = (const float*)d_in[1];
    const float* bq = (const float*)d_in[2];
    const float* Wk = (const float*)d_in[3];
    const float* bk = (const float*)d_in[4];   // cancels in softmax
    float* out = (float*)d_out;
    (void)bk;

    fp16 *xh, *xl, *wqt, *wqtl, *wkt, *wktl, *mth, *mtl, *th, *tl, *s16;
    float *wp, *wv, *vv;
    cudaGetSymbolAddress((void**)&xh,   g_xh);
    cudaGetSymbolAddress((void**)&xl,   g_xl);
    cudaGetSymbolAddress((void**)&wqt,  g_wqt);
    cudaGetSymbolAddress((void**)&wqtl, g_wqtl);
    cudaGetSymbolAddress((void**)&wkt,  g_wkt);
    cudaGetSymbolAddress((void**)&wktl, g_wktl);
    cudaGetSymbolAddress((void**)&mth,  g_mth);
    cudaGetSymbolAddress((void**)&mtl,  g_mtl);
    cudaGetSymbolAddress((void**)&th,   g_th);
    cudaGetSymbolAddress((void**)&tl,   g_tl);
    cudaGetSymbolAddress((void**)&s16,  g_s16);
    cudaGetSymbolAddress((void**)&wp,   g_wp);
    cudaGetSymbolAddress((void**)&wv,   g_w);
    cudaGetSymbolAddress((void**)&vv,   g_v);

    cudaFuncSetAttribute(gemm3p, cudaFuncAttributeMaxDynamicSharedMemorySize, SMEM3);
    cudaFuncSetAttribute(gemm1p, cudaFuncAttributeMaxDynamicSharedMemorySize, SMEM1);

    // Prep: 5 launches total.
    wvec_part2<<<dim3(DIM / 256, 64), 256>>>(Wk, bq, wp);
    wvec_red2<<<DIM / 256, 256>>>(wp, wv);
    split_vvec<<<N_TOK, 256>>>(x, wv, xh, xl, vv);
    transpose_split_w2<<<dim3(DIM / 32, DIM / 32, 2), dim3(32, 8)>>>(
        Wq, Wk, wqt, wqtl, wkt, wktl);

    // Mt = Wk^T @ Wq, split out. M=N=K=1024
    gemm3p<<<dim3(DIM / 128, DIM / 128), NTH, SMEM3>>>(
        wkt, wktl, wqt, wqtl, mth, mtl, DIM, DIM, DIM);

    // t = x @ M, split out. M=4096,N=1024,K=1024
    gemm3p<<<dim3(DIM / 128, N_TOK / 128), NTH, SMEM3>>>(
        xh, xl, mth, mtl, th, tl, N_TOK, DIM, DIM);

    // approx scores = th @ xh^T (1-pass, fp16 accumulate, occ-2), fp16 out
    gemm1p<<<dim3(N_TOK / 128, N_TOK / 128), NTH, SMEM1>>>(
        th, xh, s16, N_TOK, N_TOK, DIM);

    // fused: candidates, exact rescore, softmax, sparse output
    fused_attn_out<<<N_TOK, 256>>>(s16, vv, th, tl, x, out);
}

// round 17
// speedup vs baseline: 1.0702x; 1.0567x over previous
#include <cuda_runtime.h>
#include <cuda_fp16.h>
#include <math_constants.h>
#include <cstdint>

#define N_TOK 4096
#define DIM   1024

typedef __half fp16;

// ---------------------------------------------------------------------------
// Scratch (device globals; no allocation allowed)
// ---------------------------------------------------------------------------
__device__ fp16  g_xh [(size_t)N_TOK * DIM];
__device__ fp16  g_xl [(size_t)N_TOK * DIM];
__device__ fp16  g_wqt[(size_t)DIM * DIM];
__device__ fp16  g_wqtl[(size_t)DIM * DIM];
__device__ fp16  g_wkt[(size_t)DIM * DIM];
__device__ fp16  g_wktl[(size_t)DIM * DIM];
__device__ fp16  g_mth[(size_t)DIM * DIM];
__device__ fp16  g_mtl[(size_t)DIM * DIM];
__device__ float g_mtp[2 * (size_t)DIM * DIM];  // Mt split-K fp32 partials
__device__ fp16  g_th [(size_t)N_TOK * DIM];
__device__ fp16  g_tl [(size_t)N_TOK * DIM];
__device__ fp16  g_s16[(size_t)N_TOK * N_TOK];  // approx scores (fp16)
__device__ float g_wp [64 * DIM];                // wvec partials
__device__ float g_w  [DIM];
__device__ float g_v  [N_TOK];

// ---------------------------------------------------------------------------
// Helpers
// ---------------------------------------------------------------------------
__device__ __forceinline__ uint32_t smem_to_u32(const void* p) {
    uint32_t a;
    asm("{ .reg .u64 t; cvta.to.shared.u64 t, %1; cvt.u32.u64 %0, t; }"
        : "=r"(a) : "l"(p));
    return a;
}

__device__ __forceinline__ void cp_async16(uint32_t dst, const void* src) {
    asm volatile("cp.async.cg.shared.global [%0], [%1], 16;"
        :: "r"(dst), "l"(src) : "memory");
}
#define CP_COMMIT() asm volatile("cp.async.commit_group;" ::: "memory")
#define CP_WAIT(n)  asm volatile("cp.async.wait_group %0;" :: "n"(n) : "memory")

__device__ __forceinline__ void ldmx4(uint32_t r[4], uint32_t addr) {
    asm volatile("ldmatrix.sync.aligned.m8n8.x4.shared.b16 {%0,%1,%2,%3}, [%4];"
        : "=r"(r[0]), "=r"(r[1]), "=r"(r[2]), "=r"(r[3]) : "r"(addr));
}

__device__ __forceinline__ void mma_f16(float d[4], const uint32_t a[4],
                                        uint32_t b0, uint32_t b1) {
    asm volatile(
        "mma.sync.aligned.m16n8k16.row.col.f32.f16.f16.f32 "
        "{%0,%1,%2,%3}, {%4,%5,%6,%7}, {%8,%9}, {%0,%1,%2,%3};"
        : "+f"(d[0]), "+f"(d[1]), "+f"(d[2]), "+f"(d[3])
        : "r"(a[0]), "r"(a[1]), "r"(a[2]), "r"(a[3]), "r"(b0), "r"(b1));
}

// fp16-accumulator HMMA (filter-grade)
__device__ __forceinline__ void mma_f16a(uint32_t d[2], const uint32_t a[4],
                                         uint32_t b0, uint32_t b1) {
    asm volatile(
        "mma.sync.aligned.m16n8k16.row.col.f16.f16.f16.f16 "
        "{%0,%1}, {%2,%3,%4,%5}, {%6,%7}, {%0,%1};"
        : "+r"(d[0]), "+r"(d[1])
        : "r"(a[0]), "r"(a[1]), "r"(a[2]), "r"(a[3]), "r"(b0), "r"(b1));
}

__device__ __forceinline__ void split2h(float v, fp16& h, fp16& l) {
    h = __float2half_rn(v);
    l = __float2half_rn(v - __half2float(h));
}

// ---------------------------------------------------------------------------
// 3-pass split-fp16 GEMM: C[M,N] = A[M,K] @ B[N,K]^T (fp32 effective)
// Single-barrier mainloop: wait -> sync -> prefetch(c+2) -> mma.
// kz/Ksub: process K range [kz*Ksub, (kz+1)*Ksub). If Cp != null, write fp32
// partials to Cp + kz*M*N (split-K mode); else split to (Ch, Cl).
// ---------------------------------------------------------------------------
#define TILE_B   16384u
#define STG3_B   (4u * TILE_B)
#define SMEM3    (3u * STG3_B)    // 192 KB
#define NTH      512

__global__ __launch_bounds__(NTH, 1)
void gemm3p(const fp16* __restrict__ Ah_, const fp16* __restrict__ Al_,
            const fp16* __restrict__ Bh_, const fp16* __restrict__ Bl_,
            fp16* __restrict__ Ch, fp16* __restrict__ Cl,
            float* __restrict__ Cp,
            int M, int N, int K, int Ksub)
{
    extern __shared__ char smem_raw[];
    const uint32_t sbase = smem_to_u32(smem_raw);

    const int tid  = threadIdx.x;
    const int w    = tid >> 5;
    const int lane = tid & 31;
    const int bx = blockIdx.x, by = blockIdx.y;
    const int kz = blockIdx.z;
    const int wm = (w >> 2) * 32;
    const int wn = (w & 3) * 32;

    const size_t kbase = (size_t)kz * Ksub;
    const fp16* gAh = Ah_ + (size_t)by * 128 * K + kbase;
    const fp16* gAl = Al_ + (size_t)by * 128 * K + kbase;
    const fp16* gBh = Bh_ + (size_t)bx * 128 * K + kbase;
    const fp16* gBl = Bl_ + (size_t)bx * 128 * K + kbase;

    float acc[2][4][4];
#pragma unroll
    for (int i = 0; i < 2; i++)
#pragma unroll
        for (int j = 0; j < 4; j++)
#pragma unroll
            for (int k = 0; k < 4; k++) acc[i][j][k] = 0.0f;

    uint32_t lso[2];
    size_t lgo[2];
#pragma unroll
    for (int i = 0; i < 2; i++) {
        int idx = tid + i * NTH;
        int row = idx >> 3;
        int u   = idx & 7;
        lso[i] = (uint32_t)row * 128u + (uint32_t)((u ^ (row & 7)) << 4);
        lgo[i] = (size_t)row * K + (size_t)u * 8;
    }

    const int NC = Ksub >> 6;

    auto load_stage = [&](int c, int s) {
        const size_t kofs = (size_t)c << 6;
        const uint32_t sb = sbase + (uint32_t)s * STG3_B;
#pragma unroll
        for (int i = 0; i < 2; i++) {
            cp_async16(sb + 0u * TILE_B + lso[i], gAh + lgo[i] + kofs);
            cp_async16(sb + 1u * TILE_B + lso[i], gAl + lgo[i] + kofs);
            cp_async16(sb + 2u * TILE_B + lso[i], gBh + lgo[i] + kofs);
            cp_async16(sb + 3u * TILE_B + lso[i], gBl + lgo[i] + kofs);
        }
    };

    load_stage(0, 0); CP_COMMIT();
    if (NC > 1) load_stage(1, 1);
    CP_COMMIT();

    const int lr = lane & 15;
    const int lu = lane >> 4;

    for (int c = 0; c < NC; c++) {
        CP_WAIT(1);
        __syncthreads();

        if (c + 2 < NC) load_stage(c + 2, (c + 2) % 3);
        CP_COMMIT();

        const uint32_t st  = sbase + (uint32_t)(c % 3) * STG3_B;
        const uint32_t Ahb = st;
        const uint32_t Alb = st + 1u * TILE_B;
        const uint32_t Bhb = st + 2u * TILE_B;
        const uint32_t Blb = st + 3u * TILE_B;

#pragma unroll
        for (int ks = 0; ks < 4; ks++) {
            uint32_t ah[2][4], al[2][4], bh[2][4], bl[2][4];
            const int unit = ks * 2 + lu;
#pragma unroll
            for (int mt = 0; mt < 2; mt++) {
                int row = wm + mt * 16 + lr;
                uint32_t off = (uint32_t)row * 128u
                             + (uint32_t)((unit ^ (row & 7)) << 4);
                ldmx4(ah[mt], Ahb + off);
                ldmx4(al[mt], Alb + off);
            }
#pragma unroll
            for (int nt = 0; nt < 2; nt++) {
                int row = wn + nt * 16 + lr;
                uint32_t off = (uint32_t)row * 128u
                             + (uint32_t)((unit ^ (row & 7)) << 4);
                ldmx4(bh[nt], Bhb + off);
                ldmx4(bl[nt], Blb + off);
            }
#pragma unroll
            for (int mt = 0; mt < 2; mt++) {
#pragma unroll
                for (int n8 = 0; n8 < 4; n8++) {
                    const int nt = n8 >> 1, sel = n8 & 1;
                    const uint32_t b0h = bh[nt][sel], b1h = bh[nt][sel + 2];
                    const uint32_t b0l = bl[nt][sel], b1l = bl[nt][sel + 2];
                    mma_f16(acc[mt][n8], ah[mt], b0h, b1h);
                    mma_f16(acc[mt][n8], ah[mt], b0l, b1l);
                    mma_f16(acc[mt][n8], al[mt], b0h, b1h);
                }
            }
        }
    }

    const int g  = lane >> 2;
    const int tc = lane & 3;
    float* Cpz = Cp ? (Cp + (size_t)kz * M * N) : nullptr;
#pragma unroll
    for (int mt = 0; mt < 2; mt++) {
#pragma unroll
        for (int n8 = 0; n8 < 4; n8++) {
            const int r0 = by * 128 + wm + mt * 16 + g;
            const int r1 = r0 + 8;
            const int col = bx * 128 + wn + n8 * 8 + tc * 2;
            float c0 = acc[mt][n8][0], c1 = acc[mt][n8][1];
            float c2 = acc[mt][n8][2], c3 = acc[mt][n8][3];
            if (Cpz) {
                float2 v0; v0.x = c0; v0.y = c1;
                float2 v1; v1.x = c2; v1.y = c3;
                *(float2*)(Cpz + (size_t)r0 * N + col) = v0;
                *(float2*)(Cpz + (size_t)r1 * N + col) = v1;
            } else {
                fp16 h0,l0,h1,l1,h2,l2,h3,l3;
                split2h(c0, h0, l0); split2h(c1, h1, l1);
                split2h(c2, h2, l2); split2h(c3, h3, l3);
                *(__half2*)(Ch + (size_t)r0 * N + col) = __halves2half2(h0, h1);
                *(__half2*)(Cl + (size_t)r0 * N + col) = __halves2half2(l0, l1);
                *(__half2*)(Ch + (size_t)r1 * N + col) = __halves2half2(h2, h3);
                *(__half2*)(Cl + (size_t)r1 * N + col) = __halves2half2(l2, l3);
            }
        }
    }
}

// ---------------------------------------------------------------------------
// Split-K combine: C = P0 + P1, emitted as (hi, lo) fp16 split.
// ---------------------------------------------------------------------------
__global__ __launch_bounds__(256)
void combine_splitk(const float* __restrict__ P, fp16* __restrict__ Ch,
                    fp16* __restrict__ Cl, int total4)
{
    int i = blockIdx.x * 256 + threadIdx.x;
    if (i >= total4) return;
    float4 a = ((const float4*)P)[i];
    float4 b = ((const float4*)(P + (size_t)DIM * DIM))[i];
    float v0 = a.x + b.x, v1 = a.y + b.y, v2 = a.z + b.z, v3 = a.w + b.w;
    fp16 h0,l0,h1,l1,h2,l2,h3,l3;
    split2h(v0, h0, l0); split2h(v1, h1, l1);
    split2h(v2, h2, l2); split2h(v3, h3, l3);
    __half2 ha = __halves2half2(h0, h1), hb = __halves2half2(h2, h3);
    __half2 la = __halves2half2(l0, l1), lb = __halves2half2(l2, l3);
    uint2 hu; hu.x = *(uint32_t*)&ha; hu.y = *(uint32_t*)&hb;
    uint2 lu; lu.x = *(uint32_t*)&la; lu.y = *(uint32_t*)&lb;
    ((uint2*)Ch)[i] = hu;
    ((uint2*)Cl)[i] = lu;
}

// ---------------------------------------------------------------------------
// 1-pass fp16 GEMM with fp16 ACCUMULATION (filter-grade): S16 = fp16(A @ B^T).
// 3-stage single-barrier pipeline, 96 KB smem -> 2 CTAs/SM.
// ---------------------------------------------------------------------------
#define STG1_B (2u * TILE_B)
#define SMEM1  (3u * STG1_B)     // 96 KB

__global__ __launch_bounds__(NTH, 2)
void gemm1p(const fp16* __restrict__ Ah_, const fp16* __restrict__ Bh_,
            fp16* __restrict__ S16, int M, int N, int K)
{
    extern __shared__ char smem_raw[];
    const uint32_t sbase = smem_to_u32(smem_raw);

    const int tid  = threadIdx.x;
    const int w    = tid >> 5;
    const int lane = tid & 31;
    const int bx = blockIdx.x, by = blockIdx.y;
    const int wm = (w >> 2) * 32;
    const int wn = (w & 3) * 32;

    const fp16* gAh = Ah_ + (size_t)by * 128 * K;
    const fp16* gBh = Bh_ + (size_t)bx * 128 * K;

    uint32_t acc[2][4][2];
#pragma unroll
    for (int i = 0; i < 2; i++)
#pragma unroll
        for (int j = 0; j < 4; j++) {
            acc[i][j][0] = 0u;
            acc[i][j][1] = 0u;
        }

    uint32_t lso[2];
    size_t lgo[2];
#pragma unroll
    for (int i = 0; i < 2; i++) {
        int idx = tid + i * NTH;
        int row = idx >> 3;
        int u   = idx & 7;
        lso[i] = (uint32_t)row * 128u + (uint32_t)((u ^ (row & 7)) << 4);
        lgo[i] = (size_t)row * K + (size_t)u * 8;
    }

    const int NC = K >> 6;

    auto load_stage = [&](int c, int s) {
        const size_t kofs = (size_t)c << 6;
        const uint32_t sb = sbase + (uint32_t)s * STG1_B;
#pragma unroll
        for (int i = 0; i < 2; i++) {
            cp_async16(sb + 0u * TILE_B + lso[i], gAh + lgo[i] + kofs);
            cp_async16(sb + 1u * TILE_B + lso[i], gBh + lgo[i] + kofs);
        }
    };

    load_stage(0, 0); CP_COMMIT();
    if (NC > 1) load_stage(1, 1);
    CP_COMMIT();

    const int lr = lane & 15;
    const int lu = lane >> 4;

    for (int c = 0; c < NC; c++) {
        CP_WAIT(1);
        __syncthreads();

        if (c + 2 < NC) load_stage(c + 2, (c + 2) % 3);
        CP_COMMIT();

        const uint32_t st  = sbase + (uint32_t)(c % 3) * STG1_B;
        const uint32_t Ahb = st;
        const uint32_t Bhb = st + 1u * TILE_B;

#pragma unroll
        for (int ks = 0; ks < 4; ks++) {
            uint32_t ah[2][4], bh[2][4];
            const int unit = ks * 2 + lu;
#pragma unroll
            for (int mt = 0; mt < 2; mt++) {
                int row = wm + mt * 16 + lr;
                uint32_t off = (uint32_t)row * 128u
                             + (uint32_t)((unit ^ (row & 7)) << 4);
                ldmx4(ah[mt], Ahb + off);
            }
#pragma unroll
            for (int nt = 0; nt < 2; nt++) {
                int row = wn + nt * 16 + lr;
                uint32_t off = (uint32_t)row * 128u
                             + (uint32_t)((unit ^ (row & 7)) << 4);
                ldmx4(bh[nt], Bhb + off);
            }
#pragma unroll
            for (int mt = 0; mt < 2; mt++) {
#pragma unroll
                for (int n8 = 0; n8 < 4; n8++) {
                    const int nt = n8 >> 1, sel = n8 & 1;
                    mma_f16a(acc[mt][n8], ah[mt], bh[nt][sel], bh[nt][sel + 2]);
                }
            }
        }
    }

    const int g  = lane >> 2;
    const int tc = lane & 3;
#pragma unroll
    for (int mt = 0; mt < 2; mt++) {
#pragma unroll
        for (int n8 = 0; n8 < 4; n8++) {
            const int r0 = by * 128 + wm + mt * 16 + g;
            const int r1 = r0 + 8;
            const int col = bx * 128 + wn + n8 * 8 + tc * 2;
            *(uint32_t*)(S16 + (size_t)r0 * N + col) = acc[mt][n8][0];
            *(uint32_t*)(S16 + (size_t)r1 * N + col) = acc[mt][n8][1];
        }
    }
}

// ---------------------------------------------------------------------------
// Fused: x row -> (hi, lo) fp16 split AND v[row] = x[row] . w
// ---------------------------------------------------------------------------
__global__ __launch_bounds__(256)
void split_vvec(const float* __restrict__ x, const float* __restrict__ w,
                fp16* __restrict__ oh, fp16* __restrict__ ol,
                float* __restrict__ v)
{
    __shared__ float red[8];
    const int row = blockIdx.x;
    const int tid = threadIdx.x;
    const int lane = tid & 31;
    const int wid = tid >> 5;

    float4 xv = ((const float4*)(x + (size_t)row * DIM))[tid];
    float4 wv = ((const float4*)w)[tid];

    fp16 h0,l0,h1,l1,h2,l2,h3,l3;
    split2h(xv.x, h0, l0); split2h(xv.y, h1, l1);
    split2h(xv.z, h2, l2); split2h(xv.w, h3, l3);
    __half2 ha = __halves2half2(h0, h1), hb = __halves2half2(h2, h3);
    __half2 la = __halves2half2(l0, l1), lb = __halves2half2(l2, l3);
    uint2 hu; hu.x = *(uint32_t*)&ha; hu.y = *(uint32_t*)&hb;
    uint2 lu; lu.x = *(uint32_t*)&la; lu.y = *(uint32_t*)&lb;
    ((uint2*)(oh + (size_t)row * DIM))[tid] = hu;
    ((uint2*)(ol + (size_t)row * DIM))[tid] = lu;

    float s = xv.x * wv.x + xv.y * wv.y + xv.z * wv.z + xv.w * wv.w;
#pragma unroll
    for (int o = 16; o > 0; o >>= 1)
        s += __shfl_xor_sync(0xffffffffu, s, o);
    if (lane == 0) red[wid] = s;
    __syncthreads();
    if (wid == 0) {
        float t = (lane < 8) ? red[lane] : 0.0f;
#pragma unroll
        for (int o = 4; o > 0; o >>= 1)
            t += __shfl_xor_sync(0xffffffffu, t, o);
        if (lane == 0) v[row] = t;
    }
}

// ---------------------------------------------------------------------------
// Both W transposes in one launch: z=0 -> Wq, z=1 -> Wk.
// ---------------------------------------------------------------------------
__global__ __launch_bounds__(256)
void transpose_split_w2(const float* __restrict__ Wq, const float* __restrict__ Wk,
                        fp16* __restrict__ qh, fp16* __restrict__ ql,
                        fp16* __restrict__ kh, fp16* __restrict__ kl)
{
    __shared__ float t[32][33];
    const float* in = blockIdx.z ? Wk : Wq;
    fp16* oh = blockIdx.z ? kh : qh;
    fp16* ol = blockIdx.z ? kl : ql;
    const int c0 = blockIdx.x * 32;
    const int r0 = blockIdx.y * 32;
    const int tx = threadIdx.x;
    const int ty = threadIdx.y;
#pragma unroll
    for (int j = 0; j < 32; j += 8)
        t[ty + j][tx] = in[(size_t)(r0 + ty + j) * DIM + c0 + tx];
    __syncthreads();
#pragma unroll
    for (int j = 0; j < 32; j += 8) {
        float v = t[tx][ty + j];
        fp16 h, l;
        split2h(v, h, l);
        size_t o = (size_t)(c0 + ty + j) * DIM + r0 + tx;
        oh[o] = h;
        ol[o] = l;
    }
}

// ---------------------------------------------------------------------------
// wvec 2-stage, MLP-rich: partials then reduce.
// ---------------------------------------------------------------------------
__global__ __launch_bounds__(256)
void wvec_part2(const float* __restrict__ Wk, const float* __restrict__ bq,
                float* __restrict__ wp)
{
    const int e = blockIdx.x * 256 + threadIdx.x;
    const int p = blockIdx.y;           // 0..63
    const int a0 = p * 16;
    float s = 0.0f;
#pragma unroll
    for (int i = 0; i < 16; i++)
        s += bq[a0 + i] * Wk[(size_t)(a0 + i) * DIM + e];
    wp[(size_t)p * DIM + e] = s;
}

__global__ __launch_bounds__(256)
void wvec_red2(const float* __restrict__ wp, float* __restrict__ w)
{
    const int e = blockIdx.x * 256 + threadIdx.x;
    float s = 0.0f;
#pragma unroll
    for (int p = 0; p < 64; p++)
        s += wp[(size_t)p * DIM + e];
    w[e] = s;
}

// ---------------------------------------------------------------------------
// Fused per-row (256 threads): fp16 approx logits (S + v) -> threshold
// candidates -> exact fp32 rescore -> softmax -> out[row] = sum w_c * x[c].
// ---------------------------------------------------------------------------
#define CAP    1024
#define MARGIN 24.5f

__global__ __launch_bounds__(256, 2)
void fused_attn_out(const fp16* __restrict__ S, const float* __restrict__ vcol,
                    const fp16* __restrict__ th_, const fp16* __restrict__ tl_,
                    const float* __restrict__ x, float* __restrict__ out)
{
    const int row  = blockIdx.x;
    const int tid  = threadIdx.x;
    const int lane = tid & 31;
    const int wid  = tid >> 5;

    __shared__ __align__(16) float t_row[DIM];
    __shared__ int   cidx[CAP];
    __shared__ float cval[CAP];
    __shared__ float redF[8];
    __shared__ int   redI[16];
    __shared__ int   s_cnt;
    __shared__ float s_bcast;

    {
        uint2 uh = ((const uint2*)(th_ + (size_t)row * DIM))[tid];
        uint2 ul = ((const uint2*)(tl_ + (size_t)row * DIM))[tid];
        __half2 h0 = *(__half2*)&uh.x, h1 = *(__half2*)&uh.y;
        __half2 l0 = *(__half2*)&ul.x, l1 = *(__half2*)&ul.y;
        float4 tv;
        tv.x = __low2float(h0)  + __low2float(l0);
        tv.y = __high2float(h0) + __high2float(l0);
        tv.z = __low2float(h1)  + __low2float(l1);
        tv.w = __high2float(h1) + __high2float(l1);
        *(float4*)(&t_row[tid * 4]) = tv;
    }

    const fp16* Sr = S + (size_t)row * N_TOK;
    float l[4][4];
    float mx = -CUDART_INF_F;
#pragma unroll
    for (int i = 0; i < 4; i++) {
        size_t p = (size_t)(tid + i * 256) * 4;
        uint2 u = *(const uint2*)(Sr + p);
        __half2 h0 = *(__half2*)&u.x, h1 = *(__half2*)&u.y;
        float4 vv = *(const float4*)(vcol + p);
        l[i][0] = __low2float(h0)  + vv.x;
        l[i][1] = __high2float(h0) + vv.y;
        l[i][2] = __low2float(h1)  + vv.z;
        l[i][3] = __high2float(h1) + vv.w;
#pragma unroll
        for (int e = 0; e < 4; e++) mx = fmaxf(mx, l[i][e]);
    }
#pragma unroll
    for (int o = 16; o > 0; o >>= 1)
        mx = fmaxf(mx, __shfl_xor_sync(0xffffffffu, mx, o));
    if (lane == 0) redF[wid] = mx;
    __syncthreads();
    if (wid == 0) {
        float m = (lane < 8) ? redF[lane] : -CUDART_INF_F;
#pragma unroll
        for (int o = 4; o > 0; o >>= 1)
            m = fmaxf(m, __shfl_xor_sync(0xffffffffu, m, o));
        if (lane == 0) s_bcast = m;
    }
    __syncthreads();
    const float thr = s_bcast - MARGIN;

    int mycnt = 0;
#pragma unroll
    for (int i = 0; i < 4; i++)
#pragma unroll
        for (int e = 0; e < 4; e++)
            if (l[i][e] > thr) mycnt++;

    int inc = mycnt;
#pragma unroll
    for (int o = 1; o < 32; o <<= 1) {
        int n = __shfl_up_sync(0xffffffffu, inc, o);
        if (lane >= o) inc += n;
    }
    const int myoff_w = inc - mycnt;
    const int wtot = __shfl_sync(0xffffffffu, inc, 31);
    if (lane == 0) redI[wid] = wtot;
    __syncthreads();
    if (wid == 0 && lane < 8) {
        int v = redI[lane];
#pragma unroll
        for (int o = 1; o < 8; o <<= 1) {
            int n = __shfl_up_sync(0x000000ffu, v, o);
            if (lane >= o) v += n;
        }
        redI[8 + lane] = v - redI[lane];
        if (lane == 7) s_cnt = (v > CAP) ? CAP : v;
    }
    __syncthreads();

    int k = redI[8 + wid] + myoff_w;
#pragma unroll
    for (int i = 0; i < 4; i++) {
#pragma unroll
        for (int e = 0; e < 4; e++) {
            if (l[i][e] > thr) {
                if (k < CAP) cidx[k] = (tid + i * 256) * 4 + e;
                k++;
            }
        }
    }
    __syncthreads();

    const int cnt = s_cnt;

    for (int c = wid; c < cnt; c += 8) {
        const float* xj = x + (size_t)cidx[c] * DIM;
        float s = 0.0f;
#pragma unroll
        for (int it = 0; it < 8; it++) {
            int d = (it * 32 + lane) * 4;
            float4 a = *(const float4*)(&t_row[d]);
            float4 b = *(const float4*)(xj + d);
            s += a.x * b.x + a.y * b.y + a.z * b.z + a.w * b.w;
        }
#pragma unroll
        for (int o = 16; o > 0; o >>= 1)
            s += __shfl_xor_sync(0xffffffffu, s, o);
        if (lane == 0) cval[c] = s + vcol[cidx[c]];
    }
    __syncthreads();

    float m2 = -CUDART_INF_F;
    for (int c = tid; c < cnt; c += 256) m2 = fmaxf(m2, cval[c]);
#pragma unroll
    for (int o = 16; o > 0; o >>= 1)
        m2 = fmaxf(m2, __shfl_xor_sync(0xffffffffu, m2, o));
    if (lane == 0) redF[wid] = m2;
    __syncthreads();
    if (wid == 0) {
        float m = (lane < 8) ? redF[lane] : -CUDART_INF_F;
#pragma unroll
        for (int o = 4; o > 0; o >>= 1)
            m = fmaxf(m, __shfl_xor_sync(0xffffffffu, m, o));
        if (lane == 0) s_bcast = m;
    }
    __syncthreads();
    m2 = s_bcast;
    __syncthreads();

    float sum = 0.0f;
    for (int c = tid; c < cnt; c += 256) {
        float e = __expf(cval[c] - m2);
        cval[c] = e;
        sum += e;
    }
#pragma unroll
    for (int o = 16; o > 0; o >>= 1)
        sum += __shfl_xor_sync(0xffffffffu, sum, o);
    if (lane == 0) redF[wid] = sum;
    __syncthreads();
    if (wid == 0) {
        float s = (lane < 8) ? redF[lane] : 0.0f;
#pragma unroll
        for (int o = 4; o > 0; o >>= 1)
            s += __shfl_xor_sync(0xffffffffu, s, o);
        if (lane == 0) s_bcast = s;
    }
    __syncthreads();
    const float inv = 1.0f / s_bcast;

    float4 acc; acc.x = 0.0f; acc.y = 0.0f; acc.z = 0.0f; acc.w = 0.0f;
    const int col = tid * 4;
    for (int c = 0; c < cnt; c++) {
        const float wc = cval[c] * inv;
        float4 xv = *(const float4*)(x + (size_t)cidx[c] * DIM + col);
        acc.x += wc * xv.x; acc.y += wc * xv.y;
        acc.z += wc * xv.z; acc.w += wc * xv.w;
    }
    *(float4*)(out + (size_t)row * DIM + col) = acc;
}

// ---------------------------------------------------------------------------
// Launch
// ---------------------------------------------------------------------------
extern "C" void kernel_launch(void* const* d_in, const int* in_sizes, int n_in,
                              void* d_out, int out_size)
{
    const float* x  = (const float*)d_in[0];
    const float* Wq = (const float*)d_in[1];
    const float* bq = (const float*)d_in[2];
    const float* Wk = (const float*)d_in[3];
    const float* bk = (const float*)d_in[4];   // cancels in softmax
    float* out = (float*)d_out;
    (void)bk;

    fp16 *xh, *xl, *wqt, *wqtl, *wkt, *wktl, *mth, *mtl, *th, *tl, *s16;
    float *mtp, *wp, *wv, *vv;
    cudaGetSymbolAddress((void**)&xh,   g_xh);
    cudaGetSymbolAddress((void**)&xl,   g_xl);
    cudaGetSymbolAddress((void**)&wqt,  g_wqt);
    cudaGetSymbolAddress((void**)&wqtl, g_wqtl);
    cudaGetSymbolAddress((void**)&wkt,  g_wkt);
    cudaGetSymbolAddress((void**)&wktl, g_wktl);
    cudaGetSymbolAddress((void**)&mth,  g_mth);
    cudaGetSymbolAddress((void**)&mtl,  g_mtl);
    cudaGetSymbolAddress((void**)&mtp,  g_mtp);
    cudaGetSymbolAddress((void**)&th,   g_th);
    cudaGetSymbolAddress((void**)&tl,   g_tl);
    cudaGetSymbolAddress((void**)&s16,  g_s16);
    cudaGetSymbolAddress((void**)&wp,   g_wp);
    cudaGetSymbolAddress((void**)&wv,   g_w);
    cudaGetSymbolAddress((void**)&vv,   g_v);

    cudaFuncSetAttribute(gemm3p, cudaFuncAttributeMaxDynamicSharedMemorySize, SMEM3);
    cudaFuncSetAttribute(gemm1p, cudaFuncAttributeMaxDynamicSharedMemorySize, SMEM1);

    // Prep
    wvec_part2<<<dim3(DIM / 256, 64), 256>>>(Wk, bq, wp);
    wvec_red2<<<DIM / 256, 256>>>(wp, wv);
    split_vvec<<<N_TOK, 256>>>(x, wv, xh, xl, vv);
    transpose_split_w2<<<dim3(DIM / 32, DIM / 32, 2), dim3(32, 8)>>>(
        Wq, Wk, wqt, wqtl, wkt, wktl);

    // Mt = Wk^T @ Wq, split-K=2 (128 CTAs) -> fp32 partials -> combine.
    gemm3p<<<dim3(DIM / 128, DIM / 128, 2), NTH, SMEM3>>>(
        wkt, wktl, wqt, wqtl, nullptr, nullptr, mtp, DIM, DIM, DIM, DIM / 2);
    combine_splitk<<<(DIM * DIM / 4 + 255) / 256, 256>>>(
        mtp, mth, mtl, DIM * DIM / 4);

    // t = x @ M, split out. M=4096,N=1024,K=1024
    gemm3p<<<dim3(DIM / 128, N_TOK / 128, 1), NTH, SMEM3>>>(
        xh, xl, mth, mtl, th, tl, nullptr, N_TOK, DIM, DIM, DIM);

    // approx scores = th @ xh^T (1-pass, fp16 accumulate, occ-2), fp16 out
    gemm1p<<<dim3(N_TOK / 128, N_TOK / 128), NTH, SMEM1>>>(
        th, xh, s16, N_TOK, N_TOK, DIM);

    // fused: candidates, exact rescore, softmax, sparse output
    fused_attn_out<<<N_TOK, 256>>>(s16, vv, th, tl, x, out);
}